// round 10
// baseline (speedup 1.0000x reference)
#include <cuda_runtime.h>
#include <cuda_bf16.h>
#include <math.h>
#include <stdint.h>

#define GMM_D 64
#define GMM_K 64
#define BS    128
#define TPB   256
#define NJ2   16          // ulonglong2 steps (J=64 floats = 32 pairs = 16 ull2)
#define RX    129         // sX row stride (ull2)
#define RW    65          // sW row stride (ull2)
#define RSO   144         // sO row stride (floats) — disjoint bank sets for the 2 k-groups

typedef unsigned long long ull;

__device__ __forceinline__ ull fma2(ull a, ull b, ull c) {
    ull d; asm("fma.rn.f32x2 %0, %1, %2, %3;" : "=l"(d) : "l"(a), "l"(b), "l"(c)); return d;
}
__device__ __forceinline__ ull pack2(float lo, float hi) {
    ull r; asm("mov.b64 %0, {%1, %2};" : "=l"(r) : "f"(lo), "f"(hi)); return r;
}
__device__ __forceinline__ void unpack2(ull v, float& lo, float& hi) {
    asm("mov.b64 {%0, %1}, %2;" : "=f"(lo), "=f"(hi) : "l"(v));
}

// smem (bytes):
//   [0, 36864)        sX: ull2[16][129] (33024 B used) / sO overlay: float[64][144]
//   [36864, 53504)    sWB: ull2[16][65]   B  = mu*e^{-lv}
//   [53504, 70144)    sWA: ull2[16][65]   A' = -0.5*e^{-lv}
//   [70144, 70400)    sC: float[64]
//   [70400, 70912)    sLse: float[128]
//   [70912, 70928)    sFlag
#define OFF_X    0
#define OFF_WB   36864
#define OFF_WA   53504
#define OFF_C    70144
#define OFF_LSE  70400
#define OFF_FLAG 70912
#define SMEM_TOTAL 70928

__global__ void __launch_bounds__(TPB, 2)
gmm_fused(const float* __restrict__ X, const float* __restrict__ mu,
          const float* __restrict__ lv, const float* __restrict__ lp,
          float* __restrict__ out, int N) {
    extern __shared__ char sm[];
    ulonglong2* sX  = (ulonglong2*)(sm + OFF_X);
    ulonglong2* sWB = (ulonglong2*)(sm + OFF_WB);
    ulonglong2* sWA = (ulonglong2*)(sm + OFF_WA);
    float* sC   = (float*)(sm + OFF_C);
    float* sLse = (float*)(sm + OFF_LSE);
    int*   sFlag= (int*)(sm + OFF_FLAG);
    float* sO   = (float*)(sm + OFF_X);       // overlay after GEMM

    const int t  = threadIdx.x;
    const int n0 = blockIdx.x * BS;

    if (t == 0) *sFlag = 0;
    __syncthreads();

    // ---- stage W tiles (jp2-major) + logvar k-uniformity check ----
    {
        const float4* mu4 = (const float4*)mu;
        const float4* lv4 = (const float4*)lv;
        int bad = 0;
        #pragma unroll
        for (int i = 0; i < 4; i++) {
            int idx = i * TPB + t;            // 0..1023
            int jp2 = idx & 15;
            int k   = idx >> 4;
            float4 l  = lv4[k * 16 + jp2];
            float4 m  = mu4[k * 16 + jp2];
            float4 l0 = lv4[jp2];             // row 0
            bad |= (__float_as_int(l.x) != __float_as_int(l0.x)) |
                   (__float_as_int(l.y) != __float_as_int(l0.y)) |
                   (__float_as_int(l.z) != __float_as_int(l0.z)) |
                   (__float_as_int(l.w) != __float_as_int(l0.w));
            float e0 = __expf(-l.x), e1 = __expf(-l.y);
            float e2 = __expf(-l.z), e3 = __expf(-l.w);
            ulonglong2 B, A;
            B.x = pack2(m.x * e0, m.y * e1);     B.y = pack2(m.z * e2, m.w * e3);
            A.x = pack2(-0.5f * e0, -0.5f * e1); A.y = pack2(-0.5f * e2, -0.5f * e3);
            sWB[jp2 * RW + k] = B;
            sWA[jp2 * RW + k] = A;
        }
        if (bad) atomicOr(sFlag, 1);
        if (t < GMM_K) {
            float s = 0.f;
            #pragma unroll 8
            for (int d = 0; d < GMM_D; d++) {
                float l = lv[t * GMM_D + d];
                float m = mu[t * GMM_D + d];
                s += l + m * m * __expf(-l);
            }
            sC[t] = -0.5f * s + lp[t];
        }
    }

    // ---- stage X (jp2-major ull2): coalesced float4 global reads ----
    {
        const float4* xg4 = (const float4*)(X + (size_t)n0 * GMM_D);
        #pragma unroll
        for (int i = 0; i < 8; i++) {
            int idx = i * TPB + t;            // 0..2047
            int n   = idx >> 4;
            int jp2 = idx & 15;
            float4 v = xg4[idx];
            ulonglong2 p;
            p.x = pack2(v.x, v.y); p.y = pack2(v.z, v.w);
            sX[jp2 * RX + n] = p;
        }
    }
    __syncthreads();

    const int general = *sFlag;

    // ---- GEMM: thread tile 8 samples x 4 k ----
    const int ts = t & 15;                    // samples ts + 16m (m=0..7)
    const int tk = t >> 4;                    // k = tk + 16q    (q=0..3)

    ull acc[8][4];
    #pragma unroll
    for (int m = 0; m < 8; m++)
        #pragma unroll
        for (int q = 0; q < 4; q++) acc[m][q] = 0ull;

    {
        const ulonglong2* xb = sX + ts;
        const ulonglong2* wb = sWB + tk;
        #pragma unroll 4
        for (int jp2 = 0; jp2 < NJ2; jp2++) {
            ulonglong2 wv[4], xv[8];
            #pragma unroll
            for (int q = 0; q < 4; q++) wv[q] = wb[jp2 * RW + 16 * q];
            #pragma unroll
            for (int m = 0; m < 8; m++) xv[m] = xb[jp2 * RX + 16 * m];
            #pragma unroll
            for (int m = 0; m < 8; m++)
                #pragma unroll
                for (int q = 0; q < 4; q++) {
                    acc[m][q] = fma2(xv[m].x, wv[q].x, acc[m][q]);
                    acc[m][q] = fma2(xv[m].y, wv[q].y, acc[m][q]);
                }
        }
    }

    if (general) {
        // rare path: restage sX with x^2, then accumulate x^2 * A'
        __syncthreads();
        const float4* xg4 = (const float4*)(X + (size_t)n0 * GMM_D);
        #pragma unroll
        for (int i = 0; i < 8; i++) {
            int idx = i * TPB + t;
            int n   = idx >> 4;
            int jp2 = idx & 15;
            float4 v = xg4[idx];
            ulonglong2 p;
            p.x = pack2(v.x * v.x, v.y * v.y); p.y = pack2(v.z * v.z, v.w * v.w);
            sX[jp2 * RX + n] = p;
        }
        __syncthreads();
        const ulonglong2* xb = sX + ts;
        const ulonglong2* wb = sWA + tk;
        #pragma unroll 4
        for (int jp2 = 0; jp2 < NJ2; jp2++) {
            ulonglong2 wv[4], xv[8];
            #pragma unroll
            for (int q = 0; q < 4; q++) wv[q] = wb[jp2 * RW + 16 * q];
            #pragma unroll
            for (int m = 0; m < 8; m++) xv[m] = xb[jp2 * RX + 16 * m];
            #pragma unroll
            for (int m = 0; m < 8; m++)
                #pragma unroll
                for (int q = 0; q < 4; q++) {
                    acc[m][q] = fma2(xv[m].x, wv[q].x, acc[m][q]);
                    acc[m][q] = fma2(xv[m].y, wv[q].y, acc[m][q]);
                }
        }
    }

    // ---- finalize + scatter to sO[k][n] ----
    float w[8][4];
    #pragma unroll
    for (int q = 0; q < 4; q++) {
        float ck = sC[tk + 16 * q];
        #pragma unroll
        for (int m = 0; m < 8; m++) {
            float lo, hi; unpack2(acc[m][q], lo, hi);
            w[m][q] = lo + hi + ck;
        }
    }
    __syncthreads();                          // sX dead -> sO overlay
    #pragma unroll
    for (int q = 0; q < 4; q++) {
        const int k = tk + 16 * q;
        #pragma unroll
        for (int m = 0; m < 8; m++)
            sO[k * RSO + ts + 16 * m] = w[m][q];
    }
    __syncthreads();

    // ---- per-sample logsumexp over k (threads 0..127) ----
    if (t < BS) {
        float mx = -INFINITY;
        #pragma unroll 8
        for (int k = 0; k < GMM_K; k++) mx = fmaxf(mx, sO[k * RSO + t]);
        float s = 0.f;
        #pragma unroll 8
        for (int k = 0; k < GMM_K; k++) s += __expf(sO[k * RSO + t] - mx);
        sLse[t] = mx + __logf(s);
    }
    __syncthreads();

    // ---- coalesced float4 writeout: 8 warps cover k-rows round-robin ----
    {
        const int lane = t & 31;
        const int kq   = t >> 5;              // 0..7
        float4 L = ((const float4*)sLse)[lane];
        #pragma unroll
        for (int i = 0; i < 8; i++) {
            int k = i * 8 + kq;
            float4 v = *(const float4*)&sO[k * RSO + lane * 4];
            float4 r;
            r.x = v.x - L.x; r.y = v.y - L.y; r.z = v.z - L.z; r.w = v.w - L.w;
            *(float4*)(out + (size_t)k * N + n0 + lane * 4) = r;
        }
    }
}

extern "C" void kernel_launch(void* const* d_in, const int* in_sizes, int n_in,
                              void* d_out, int out_size) {
    const float* X  = (const float*)d_in[0];
    const float* mu = (const float*)d_in[1];
    const float* lv = (const float*)d_in[2];
    const float* lp = (const float*)d_in[3];
    float* out = (float*)d_out;

    const int K = in_sizes[3];            // 64
    const int D = in_sizes[1] / K;        // 64
    const int N = in_sizes[0] / D;        // 131072

    cudaFuncSetAttribute(gmm_fused, cudaFuncAttributeMaxDynamicSharedMemorySize, SMEM_TOTAL);
    gmm_fused<<<N / BS, TPB, SMEM_TOTAL>>>(X, mu, lv, lp, out, N);
}

// round 11
// speedup vs baseline: 1.6940x; 1.6940x over previous
#include <cuda_runtime.h>
#include <cuda_bf16.h>
#include <math.h>
#include <stdint.h>

#define GMM_D 64
#define GMM_K 64
#define BS    128
#define TPB   256
#define NJ2   16          // ulonglong2 steps (64 floats = 32 pairs = 16 ull2)
#define RX    129         // X tile row stride (ull2)
#define RW    65          // W tile row stride (ull2)
#define RRED  144         // reduction scratch row stride (floats)

typedef unsigned long long ull;

// smem offsets (bytes)
#define OFF_X0   0
#define OFF_X1   33024
#define OFF_WB   66048
#define OFF_WA   82688
#define OFF_RED  99328
#define OFF_C    108544
#define OFF_LSE  108800
#define OFF_FLAG 109312
#define SMEM_TOTAL 109328      // x2 CTAs = 218.7KB <= 228KB/SM

__device__ __forceinline__ ull fma2(ull a, ull b, ull c) {
    ull d; asm("fma.rn.f32x2 %0, %1, %2, %3;" : "=l"(d) : "l"(a), "l"(b), "l"(c)); return d;
}
__device__ __forceinline__ ull mul2(ull a, ull b) {
    ull d; asm("mul.rn.f32x2 %0, %1, %2;" : "=l"(d) : "l"(a), "l"(b)); return d;
}
__device__ __forceinline__ ull pack2(float lo, float hi) {
    ull r; asm("mov.b64 %0, {%1, %2};" : "=l"(r) : "f"(lo), "f"(hi)); return r;
}
__device__ __forceinline__ void unpack2(ull v, float& lo, float& hi) {
    asm("mov.b64 {%0, %1}, %2;" : "=f"(lo), "=f"(hi) : "l"(v));
}
__device__ __forceinline__ uint32_t smem_u32(const void* p) {
    uint32_t a;
    asm("{ .reg .u64 t; cvta.to.shared.u64 t, %1; cvt.u32.u64 %0, t; }" : "=r"(a) : "l"(p));
    return a;
}
__device__ __forceinline__ void cp_async16(uint32_t dst, const void* src) {
    asm volatile("cp.async.cg.shared.global [%0], [%1], 16;" :: "r"(dst), "l"(src));
}
__device__ __forceinline__ void cp_commit() {
    asm volatile("cp.async.commit_group;" ::: "memory");
}
template <int NN>
__device__ __forceinline__ void cp_wait() {
    asm volatile("cp.async.wait_group %0;" :: "n"(NN) : "memory");
}

// stage one 128-sample X tile (jp2-major ull2 layout) via cp.async
__device__ __forceinline__ void prefetch_tile(const float* __restrict__ X, int tile,
                                              char* smbase, int xoff, int t) {
    const char* src = (const char*)(X + (size_t)tile * BS * GMM_D);
    #pragma unroll
    for (int i = 0; i < 8; i++) {
        int c   = i * TPB + t;            // 0..2047 16B chunks
        int n   = c >> 4;
        int jp2 = c & 15;
        uint32_t dst = smem_u32(smbase + xoff + (jp2 * RX + n) * 16);
        cp_async16(dst, src + (size_t)c * 16);
    }
}

// ---------------------------------------------------------------------------
// Persistent fused GMM posterior. 296 CTAs, each owns ~ntiles/296 tiles.
// weighted[n,k] = sum_d x*B[k] (+ x^2*A'[k] if logvars not k-uniform) + C[k];
// k-uniform terms cancel in the log-softmax over k.
// Thread tile: 8 samples x 4 k (ts=t&15 -> n=ts+16m; tk=t>>4 -> k=tk+16q).
// ---------------------------------------------------------------------------
__global__ void __launch_bounds__(TPB, 2)
gmm_persist(const float* __restrict__ X, const float* __restrict__ mu,
            const float* __restrict__ lv, const float* __restrict__ lp,
            float* __restrict__ out, int N, int ntiles) {
    extern __shared__ char sm[];
    ulonglong2* sWB = (ulonglong2*)(sm + OFF_WB);
    ulonglong2* sWA = (ulonglong2*)(sm + OFF_WA);
    float* sRed = (float*)(sm + OFF_RED);
    float* sC   = (float*)(sm + OFF_C);
    float* sLse = (float*)(sm + OFF_LSE);
    int*   sFlag= (int*)(sm + OFF_FLAG);

    const int t  = threadIdx.x;
    const int ts = t & 15;
    const int tk = t >> 4;

    if (t == 0) *sFlag = 0;
    __syncthreads();

    // ---- stage W tiles + uniformity flag + C[k] (once per CTA) ----
    {
        const float4* mu4 = (const float4*)mu;
        const float4* lv4 = (const float4*)lv;
        int bad = 0;
        #pragma unroll
        for (int i = 0; i < 4; i++) {
            int idx = i * TPB + t;        // 0..1023
            int jp2 = idx & 15;
            int k   = idx >> 4;
            float4 l  = lv4[k * 16 + jp2];
            float4 m  = mu4[k * 16 + jp2];
            float4 l0 = lv4[jp2];
            bad |= (__float_as_int(l.x) != __float_as_int(l0.x)) |
                   (__float_as_int(l.y) != __float_as_int(l0.y)) |
                   (__float_as_int(l.z) != __float_as_int(l0.z)) |
                   (__float_as_int(l.w) != __float_as_int(l0.w));
            float e0 = __expf(-l.x), e1 = __expf(-l.y);
            float e2 = __expf(-l.z), e3 = __expf(-l.w);
            ulonglong2 B, A;
            B.x = pack2(m.x * e0, m.y * e1);     B.y = pack2(m.z * e2, m.w * e3);
            A.x = pack2(-0.5f * e0, -0.5f * e1); A.y = pack2(-0.5f * e2, -0.5f * e3);
            sWB[jp2 * RW + k] = B;
            sWA[jp2 * RW + k] = A;
        }
        if (bad) atomicOr(sFlag, 1);
        if (t < GMM_K) {
            float s = 0.f;
            #pragma unroll 8
            for (int d = 0; d < GMM_D; d++) {
                float l = lv[t * GMM_D + d];
                float m = mu[t * GMM_D + d];
                s += l + m * m * __expf(-l);
            }
            sC[t] = -0.5f * s + lp[t];
        }
    }

    // ---- prefetch first tile ----
    const int stride = gridDim.x;
    int tile = blockIdx.x;
    if (tile < ntiles) prefetch_tile(X, tile, sm, OFF_X0, t);
    cp_commit();

    int bufi = 0;
    for (; tile < ntiles; tile += stride) {
        const int nxt = tile + stride;
        if (nxt < ntiles) {
            prefetch_tile(X, nxt, sm, bufi ? OFF_X0 : OFF_X1, t);
            cp_commit();
            cp_wait<1>();
        } else {
            cp_wait<0>();
        }
        __syncthreads();                  // current X buf ready; sRed free; W ready

        const int general = *sFlag;
        const ulonglong2* xb = (const ulonglong2*)(sm + (bufi ? OFF_X1 : OFF_X0)) + ts;
        const ulonglong2* wb = sWB + tk;
        const ulonglong2* wa = sWA + tk;

        ull acc[8][4];
        #pragma unroll
        for (int m = 0; m < 8; m++)
            #pragma unroll
            for (int q = 0; q < 4; q++) acc[m][q] = 0ull;

        if (!general) {
            #pragma unroll
            for (int jp2 = 0; jp2 < NJ2; jp2++) {
                ulonglong2 wv[4], xv[8];
                #pragma unroll
                for (int q = 0; q < 4; q++) wv[q] = wb[jp2 * RW + 16 * q];
                #pragma unroll
                for (int m = 0; m < 8; m++) xv[m] = xb[jp2 * RX + 16 * m];
                #pragma unroll
                for (int m = 0; m < 8; m++)
                    #pragma unroll
                    for (int q = 0; q < 4; q++) {
                        acc[m][q] = fma2(xv[m].x, wv[q].x, acc[m][q]);
                        acc[m][q] = fma2(xv[m].y, wv[q].y, acc[m][q]);
                    }
            }
        } else {
            #pragma unroll 4
            for (int jp2 = 0; jp2 < NJ2; jp2++) {
                ulonglong2 wv[4], wv2[4], xv[8];
                #pragma unroll
                for (int q = 0; q < 4; q++) { wv[q] = wb[jp2 * RW + 16 * q];
                                              wv2[q] = wa[jp2 * RW + 16 * q]; }
                #pragma unroll
                for (int m = 0; m < 8; m++) xv[m] = xb[jp2 * RX + 16 * m];
                #pragma unroll
                for (int m = 0; m < 8; m++) {
                    ull xqx = mul2(xv[m].x, xv[m].x);
                    ull xqy = mul2(xv[m].y, xv[m].y);
                    #pragma unroll
                    for (int q = 0; q < 4; q++) {
                        acc[m][q] = fma2(xv[m].x, wv[q].x, acc[m][q]);
                        acc[m][q] = fma2(xv[m].y, wv[q].y, acc[m][q]);
                        acc[m][q] = fma2(xqx, wv2[q].x, acc[m][q]);
                        acc[m][q] = fma2(xqy, wv2[q].y, acc[m][q]);
                    }
                }
            }
        }

        // ---- finalize weighted values ----
        float w[8][4];
        #pragma unroll
        for (int q = 0; q < 4; q++) {
            float ck = sC[tk + 16 * q];
            #pragma unroll
            for (int m = 0; m < 8; m++) {
                float lo, hi; unpack2(acc[m][q], lo, hi);
                w[m][q] = lo + hi + ck;
            }
        }

        // ---- logsumexp over k: two-stage via sRed[16][144] ----
        #pragma unroll
        for (int m = 0; m < 8; m++) {
            float mx = fmaxf(fmaxf(w[m][0], w[m][1]), fmaxf(w[m][2], w[m][3]));
            sRed[tk * RRED + ts + 16 * m] = mx;
        }
        __syncthreads();
        if (t < BS) {
            float mx = -INFINITY;
            #pragma unroll
            for (int p = 0; p < 16; p++) mx = fmaxf(mx, sRed[p * RRED + t]);
            sLse[t] = mx;
        }
        __syncthreads();
        #pragma unroll
        for (int m = 0; m < 8; m++) {
            float mx = sLse[ts + 16 * m];
            float s = __expf(w[m][0] - mx) + __expf(w[m][1] - mx)
                    + __expf(w[m][2] - mx) + __expf(w[m][3] - mx);
            sRed[tk * RRED + ts + 16 * m] = s;
        }
        __syncthreads();
        if (t < BS) {
            float s = 0.f;
            #pragma unroll
            for (int p = 0; p < 16; p++) s += sRed[p * RRED + t];
            sLse[t] = sLse[t] + __logf(s);
        }
        __syncthreads();

        // ---- stores ----
        {
            const int n0 = tile * BS;
            float lse[8];
            #pragma unroll
            for (int m = 0; m < 8; m++) lse[m] = sLse[ts + 16 * m];
            #pragma unroll
            for (int q = 0; q < 4; q++) {
                float* ob = out + (size_t)(tk + 16 * q) * N + n0 + ts;
                #pragma unroll
                for (int m = 0; m < 8; m++)
                    ob[16 * m] = w[m][q] - lse[m];
            }
        }
        __syncthreads();                  // all reads of this X buf done before overwrite
        bufi ^= 1;
    }
}

extern "C" void kernel_launch(void* const* d_in, const int* in_sizes, int n_in,
                              void* d_out, int out_size) {
    const float* X  = (const float*)d_in[0];
    const float* mu = (const float*)d_in[1];
    const float* lv = (const float*)d_in[2];
    const float* lp = (const float*)d_in[3];
    float* out = (float*)d_out;

    const int K = in_sizes[3];            // 64
    const int D = in_sizes[1] / K;        // 64
    const int N = in_sizes[0] / D;        // 131072

    const int ntiles = N / BS;            // 1024
    int grid = 296;                       // 2 per SM x 148 SMs
    if (grid > ntiles) grid = ntiles;

    cudaFuncSetAttribute(gmm_persist, cudaFuncAttributeMaxDynamicSharedMemorySize, SMEM_TOTAL);
    gmm_persist<<<grid, TPB, SMEM_TOTAL>>>(X, mu, lv, lp, out, N, ntiles);
}

// round 12
// speedup vs baseline: 1.7218x; 1.0164x over previous
#include <cuda_runtime.h>
#include <cuda_bf16.h>
#include <math.h>
#include <stdint.h>

#define GMM_D 64
#define GMM_K 64
#define BS    128
#define TPB   128
#define NJ2   16          // ulonglong2 steps (64 floats = 32 pairs = 16 ull2)
#define RX    129         // X tile row stride (ull2)
#define RW    65          // W tile row stride (ull2)
#define RRED  144         // reduction scratch row stride (floats)

typedef unsigned long long ull;

// smem offsets (bytes)
#define OFF_X0   0
#define OFF_X1   33024
#define OFF_WB   66048
#define OFF_WA   82688
#define OFF_RED  99328    // 8 * 144 * 4 = 4608
#define OFF_C    103936
#define OFF_LSE  104192
#define OFF_FLAG 104704
#define SMEM_TOTAL 104720  // x2 CTAs = 209.4KB <= 228KB/SM

__device__ __forceinline__ ull fma2(ull a, ull b, ull c) {
    ull d; asm("fma.rn.f32x2 %0, %1, %2, %3;" : "=l"(d) : "l"(a), "l"(b), "l"(c)); return d;
}
__device__ __forceinline__ ull mul2(ull a, ull b) {
    ull d; asm("mul.rn.f32x2 %0, %1, %2;" : "=l"(d) : "l"(a), "l"(b)); return d;
}
__device__ __forceinline__ ull pack2(float lo, float hi) {
    ull r; asm("mov.b64 %0, {%1, %2};" : "=l"(r) : "f"(lo), "f"(hi)); return r;
}
__device__ __forceinline__ void unpack2(ull v, float& lo, float& hi) {
    asm("mov.b64 {%0, %1}, %2;" : "=f"(lo), "=f"(hi) : "l"(v));
}
__device__ __forceinline__ uint32_t smem_u32(const void* p) {
    uint32_t a;
    asm("{ .reg .u64 t; cvta.to.shared.u64 t, %1; cvt.u32.u64 %0, t; }" : "=r"(a) : "l"(p));
    return a;
}
__device__ __forceinline__ void cp_async16(uint32_t dst, const void* src) {
    asm volatile("cp.async.cg.shared.global [%0], [%1], 16;" :: "r"(dst), "l"(src));
}
__device__ __forceinline__ void cp_commit() {
    asm volatile("cp.async.commit_group;" ::: "memory");
}
template <int NN>
__device__ __forceinline__ void cp_wait() {
    asm volatile("cp.async.wait_group %0;" :: "n"(NN) : "memory");
}

// stage one 128-sample X tile (jp2-major ull2 layout) via cp.async
__device__ __forceinline__ void prefetch_tile(const float* __restrict__ X, int tile,
                                              char* smbase, int xoff, int t) {
    const char* src = (const char*)(X + (size_t)tile * BS * GMM_D);
    #pragma unroll
    for (int i = 0; i < 16; i++) {
        int c   = i * TPB + t;            // 0..2047 16B chunks
        int n   = c >> 4;
        int jp2 = c & 15;
        uint32_t dst = smem_u32(smbase + xoff + (jp2 * RX + n) * 16);
        cp_async16(dst, src + (size_t)c * 16);
    }
}

// ---------------------------------------------------------------------------
// Persistent fused GMM posterior. 296 CTAs (2/SM), double-buffered X staging.
// weighted[n,k] = sum_d x*B[k] (+ x^2*A'[k] if logvars not k-uniform) + C[k];
// k-uniform terms cancel in the log-softmax over k.
// Thread tile: 8 samples x 8 k  (ts=t&15 -> n=ts+16m, m=0..7;
//                                tk=t>>4 -> k=tk+8q,  q=0..7).
// ---------------------------------------------------------------------------
__global__ void __launch_bounds__(TPB, 2)
gmm_persist(const float* __restrict__ X, const float* __restrict__ mu,
            const float* __restrict__ lv, const float* __restrict__ lp,
            float* __restrict__ out, int N, int ntiles) {
    extern __shared__ char sm[];
    ulonglong2* sWB = (ulonglong2*)(sm + OFF_WB);
    ulonglong2* sWA = (ulonglong2*)(sm + OFF_WA);
    float* sRed = (float*)(sm + OFF_RED);
    float* sC   = (float*)(sm + OFF_C);
    float* sLse = (float*)(sm + OFF_LSE);
    int*   sFlag= (int*)(sm + OFF_FLAG);

    const int t  = threadIdx.x;
    const int ts = t & 15;
    const int tk = t >> 4;

    if (t == 0) *sFlag = 0;
    __syncthreads();

    // ---- stage W tiles + uniformity flag + C[k] (once per CTA) ----
    {
        const float4* mu4 = (const float4*)mu;
        const float4* lv4 = (const float4*)lv;
        int bad = 0;
        #pragma unroll
        for (int i = 0; i < 8; i++) {
            int idx = i * TPB + t;        // 0..1023
            int jp2 = idx & 15;
            int k   = idx >> 4;
            float4 l  = lv4[k * 16 + jp2];
            float4 m  = mu4[k * 16 + jp2];
            float4 l0 = lv4[jp2];
            bad |= (__float_as_int(l.x) != __float_as_int(l0.x)) |
                   (__float_as_int(l.y) != __float_as_int(l0.y)) |
                   (__float_as_int(l.z) != __float_as_int(l0.z)) |
                   (__float_as_int(l.w) != __float_as_int(l0.w));
            float e0 = __expf(-l.x), e1 = __expf(-l.y);
            float e2 = __expf(-l.z), e3 = __expf(-l.w);
            ulonglong2 B, A;
            B.x = pack2(m.x * e0, m.y * e1);     B.y = pack2(m.z * e2, m.w * e3);
            A.x = pack2(-0.5f * e0, -0.5f * e1); A.y = pack2(-0.5f * e2, -0.5f * e3);
            sWB[jp2 * RW + k] = B;
            sWA[jp2 * RW + k] = A;
        }
        if (bad) atomicOr(sFlag, 1);
        if (t < GMM_K) {
            float s = 0.f;
            #pragma unroll 8
            for (int d = 0; d < GMM_D; d++) {
                float l = lv[t * GMM_D + d];
                float m = mu[t * GMM_D + d];
                s += l + m * m * __expf(-l);
            }
            sC[t] = -0.5f * s + lp[t];
        }
    }

    // ---- prefetch first tile ----
    const int stride = gridDim.x;
    int tile = blockIdx.x;
    if (tile < ntiles) prefetch_tile(X, tile, sm, OFF_X0, t);
    cp_commit();

    int bufi = 0;
    for (; tile < ntiles; tile += stride) {
        const int nxt = tile + stride;
        if (nxt < ntiles) {
            prefetch_tile(X, nxt, sm, bufi ? OFF_X0 : OFF_X1, t);
            cp_commit();
            cp_wait<1>();
        } else {
            cp_wait<0>();
        }
        __syncthreads();                  // current X buf ready; sRed free

        const int general = *sFlag;
        const ulonglong2* xb = (const ulonglong2*)(sm + (bufi ? OFF_X1 : OFF_X0)) + ts;
        const ulonglong2* wb = sWB + tk;
        const ulonglong2* wa = sWA + tk;

        ull acc[8][8];
        #pragma unroll
        for (int m = 0; m < 8; m++)
            #pragma unroll
            for (int q = 0; q < 8; q++) acc[m][q] = 0ull;

        if (!general) {
            #pragma unroll
            for (int jp2 = 0; jp2 < NJ2; jp2++) {
                ulonglong2 wv[8], xv[8];
                #pragma unroll
                for (int q = 0; q < 8; q++) wv[q] = wb[jp2 * RW + 8 * q];
                #pragma unroll
                for (int m = 0; m < 8; m++) xv[m] = xb[jp2 * RX + 16 * m];
                #pragma unroll
                for (int m = 0; m < 8; m++)
                    #pragma unroll
                    for (int q = 0; q < 8; q++) {
                        acc[m][q] = fma2(xv[m].x, wv[q].x, acc[m][q]);
                        acc[m][q] = fma2(xv[m].y, wv[q].y, acc[m][q]);
                    }
            }
        } else {
            #pragma unroll 2
            for (int jp2 = 0; jp2 < NJ2; jp2++) {
                ulonglong2 wv[8], wv2[8], xv[8];
                #pragma unroll
                for (int q = 0; q < 8; q++) { wv[q]  = wb[jp2 * RW + 8 * q];
                                              wv2[q] = wa[jp2 * RW + 8 * q]; }
                #pragma unroll
                for (int m = 0; m < 8; m++) xv[m] = xb[jp2 * RX + 16 * m];
                #pragma unroll
                for (int m = 0; m < 8; m++) {
                    ull xqx = mul2(xv[m].x, xv[m].x);
                    ull xqy = mul2(xv[m].y, xv[m].y);
                    #pragma unroll
                    for (int q = 0; q < 8; q++) {
                        acc[m][q] = fma2(xv[m].x, wv[q].x, acc[m][q]);
                        acc[m][q] = fma2(xv[m].y, wv[q].y, acc[m][q]);
                        acc[m][q] = fma2(xqx, wv2[q].x, acc[m][q]);
                        acc[m][q] = fma2(xqy, wv2[q].y, acc[m][q]);
                    }
                }
            }
        }

        // ---- finalize weighted values ----
        float w[8][8];
        #pragma unroll
        for (int q = 0; q < 8; q++) {
            float ck = sC[tk + 8 * q];
            #pragma unroll
            for (int m = 0; m < 8; m++) {
                float lo, hi; unpack2(acc[m][q], lo, hi);
                w[m][q] = lo + hi + ck;
            }
        }

        // ---- logsumexp over k: two-stage via sRed[8][144] ----
        #pragma unroll
        for (int m = 0; m < 8; m++) {
            float mx = w[m][0];
            #pragma unroll
            for (int q = 1; q < 8; q++) mx = fmaxf(mx, w[m][q]);
            sRed[tk * RRED + ts + 16 * m] = mx;
        }
        __syncthreads();
        {
            float mx = -INFINITY;
            #pragma unroll
            for (int p = 0; p < 8; p++) mx = fmaxf(mx, sRed[p * RRED + t]);
            sLse[t] = mx;
        }
        __syncthreads();
        #pragma unroll
        for (int m = 0; m < 8; m++) {
            float mx = sLse[ts + 16 * m];
            float s = 0.f;
            #pragma unroll
            for (int q = 0; q < 8; q++) s += __expf(w[m][q] - mx);
            sRed[tk * RRED + ts + 16 * m] = s;
        }
        __syncthreads();
        {
            float s = 0.f;
            #pragma unroll
            for (int p = 0; p < 8; p++) s += sRed[p * RRED + t];
            sLse[t] = sLse[t] + __logf(s);
        }
        __syncthreads();

        // ---- stores ----
        {
            const int n0 = tile * BS;
            float lse[8];
            #pragma unroll
            for (int m = 0; m < 8; m++) lse[m] = sLse[ts + 16 * m];
            #pragma unroll
            for (int q = 0; q < 8; q++) {
                float* ob = out + (size_t)(tk + 8 * q) * N + n0 + ts;
                #pragma unroll
                for (int m = 0; m < 8; m++)
                    ob[16 * m] = w[m][q] - lse[m];
            }
        }
        __syncthreads();                  // all reads of this X buf done before overwrite
        bufi ^= 1;
    }
}

extern "C" void kernel_launch(void* const* d_in, const int* in_sizes, int n_in,
                              void* d_out, int out_size) {
    const float* X  = (const float*)d_in[0];
    const float* mu = (const float*)d_in[1];
    const float* lv = (const float*)d_in[2];
    const float* lp = (const float*)d_in[3];
    float* out = (float*)d_out;

    const int K = in_sizes[3];            // 64
    const int D = in_sizes[1] / K;        // 64
    const int N = in_sizes[0] / D;        // 131072

    const int ntiles = N / BS;            // 1024
    int grid = 296;                       // 2 per SM x 148 SMs
    if (grid > ntiles) grid = ntiles;

    cudaFuncSetAttribute(gmm_persist, cudaFuncAttributeMaxDynamicSharedMemorySize, SMEM_TOTAL);
    gmm_persist<<<grid, TPB, SMEM_TOTAL>>>(X, mu, lv, lp, out, N, ntiles);
}